// round 15
// baseline (speedup 1.0000x reference)
#include <cuda_runtime.h>
#include <cuda_bf16.h>
#include <cuda_fp16.h>
#include <math.h>
#include <cstdint>

#define BATCH 16
#define DIMK  1024
#define TT    2048
#define NFFT  1024
#define HOP   256
#define NBINS 513
#define NBP   520
#define MTOT  (BATCH * TT)          // 32768
#define OUTLEN (HOP * (TT - 1))     // 524032

#define NPAD  1024                  // 8 n-tiles; bins 511/512 (phase) via split_x path
#define TLM   256
#define TLN   128
#define KC    64
#define NCHG  (DIMK / KC)           // 16
#define NSPLIT 2
#define NTHR  512

#define TSEG  128
#define NSEG  (TT / TSEG)           // 16
#define NKT   (DIMK / 32)           // 32 k-tiles in split_x

static constexpr size_t ASZ = (size_t)MTOT * DIMK;
static constexpr size_t BSZ = (size_t)NPAD * DIMK;

// smem: rows of 128B data + 16B pad (conflict-free: 144 mod 128 = 16)
#define SROW        144
#define A_SPLIT     (256 * SROW)              // 36864
#define B_SPLIT     (128 * SROW)              // 18432
#define B_BASE      (2 * A_SPLIT)             // 73728
#define STAGE_BYTES (2 * A_SPLIT + 2 * B_SPLIT)  // 110592
#define NSTAGE      2
#define GEMM_SMEM   (NSTAGE * STAGE_BYTES)    // 221184

// ---------------- scratch ----------------------------------------------------
__device__ __nv_bfloat16 g_A[(size_t)NSPLIT * ASZ];
__device__ __nv_bfloat16 g_B[(size_t)NSPLIT * BSZ];
__device__ __half g_mag[(size_t)MTOT * NBP];
__device__ float g_frq[(size_t)MTOT * NBP];
__device__ __half2 g_spec[(size_t)MTOT * NBP];    // mag * e^{i phase}, fp16 pair
__device__ __half g_frames[(size_t)MTOT * NFFT];
__device__ float2 g_part[(size_t)MTOT * NKT];     // partial dots for bins 511/512
__device__ float g_segsum[BATCH][NSEG][NBP];
__device__ float g_c1024[512];
__device__ float g_s1024[512];
__device__ float g_c512[256];
__device__ float g_s512[256];
__device__ float g_winS[1024];
__device__ float g_win2[1024];

// ---------------- helpers -----------------------------------------------------
__device__ __forceinline__ uint32_t smem_u32(const void* p) {
    uint32_t a;
    asm("{ .reg .u64 t; cvta.to.shared.u64 t, %1; cvt.u32.u64 %0, t; }"
        : "=r"(a) : "l"(p));
    return a;
}
__device__ __forceinline__ void cp16(uint32_t dst, const void* src) {
    asm volatile("cp.async.cg.shared.global [%0], [%1], 16;" :: "r"(dst), "l"(src));
}
#define CP_COMMIT() asm volatile("cp.async.commit_group;")
#define CP_WAIT0()  asm volatile("cp.async.wait_group 0;" ::: "memory")

__device__ __forceinline__ void ldsm_x4(uint32_t& r0, uint32_t& r1,
                                        uint32_t& r2, uint32_t& r3, uint32_t a) {
    asm volatile("ldmatrix.sync.aligned.m8n8.x4.shared.b16 {%0,%1,%2,%3}, [%4];"
                 : "=r"(r0), "=r"(r1), "=r"(r2), "=r"(r3) : "r"(a));
}
__device__ __forceinline__ void mma_bf16(float* c, const uint32_t* a, const uint32_t* b) {
    asm volatile(
        "mma.sync.aligned.m16n8k16.row.col.f32.bf16.bf16.f32 "
        "{%0,%1,%2,%3}, {%4,%5,%6,%7}, {%8,%9}, {%0,%1,%2,%3};"
        : "+f"(c[0]), "+f"(c[1]), "+f"(c[2]), "+f"(c[3])
        : "r"(a[0]), "r"(a[1]), "r"(a[2]), "r"(a[3]), "r"(b[0]), "r"(b[1]));
}

// ---------------- table init ---------------------------------------------------
__global__ void init_tables() {
    int i = blockIdx.x * blockDim.x + threadIdx.x;
    const float TWO_PI = 6.283185307179586f;
    if (i < 512) {
        float a = TWO_PI * (float)i / 1024.0f;
        g_c1024[i] = cosf(a);
        g_s1024[i] = sinf(a);
    }
    if (i < 256) {
        float a = TWO_PI * (float)i / 512.0f;
        g_c512[i] = cosf(a);
        g_s512[i] = sinf(a);
    }
    if (i < 1024) {
        float w = 0.5f * (1.0f - cosf(TWO_PI * (float)i / 1024.0f));
        g_winS[i] = w * (1.0f / 1024.0f);
        g_win2[i] = w * w;
    }
}

// ---------------- split prep (2 terms) + extra-bin partial dots ---------------------
__device__ __forceinline__ void split2(float v, __nv_bfloat16& h0, __nv_bfloat16& h1) {
    h0 = __float2bfloat16(v);
    h1 = __float2bfloat16(v - __bfloat162float(h0));
}

__global__ void split_x_kernel(const float* __restrict__ x,
                               const float* __restrict__ Wp) {
    __shared__ float tile[32][33];
    __shared__ float w0s[32], w1s[32];
    __shared__ float red0[8][32];
    __shared__ float red1[8][32];
    int b = blockIdx.z;
    int kt = blockIdx.y;
    int k0 = kt * 32, t0 = blockIdx.x * 32;
    int tx = threadIdx.x, ty = threadIdx.y;

    if (ty == 0) {
        w0s[tx] = Wp[(size_t)511 * DIMK + k0 + tx];
        w1s[tx] = Wp[(size_t)512 * DIMK + k0 + tx];
    }
    const float* src = x + ((size_t)b * DIMK + k0) * TT + t0;
    #pragma unroll
    for (int r = 0; r < 4; r++)
        tile[ty + 8 * r][tx] = src[(size_t)(ty + 8 * r) * TT + tx];
    __syncthreads();

    // bf16 splits (transposed read)
    #pragma unroll
    for (int r = 0; r < 4; r++) {
        float v = tile[tx][ty + 8 * r];
        size_t m = (size_t)b * TT + t0 + ty + 8 * r;
        __nv_bfloat16 h0, h1;
        split2(v, h0, h1);
        size_t o = m * DIMK + k0 + tx;
        g_A[o] = h0;
        g_A[ASZ + o] = h1;
    }

    // partial dots for phase bins 511/512 (thread owns t=t0+tx, 4 k-values)
    float s0 = 0.f, s1 = 0.f;
    #pragma unroll
    for (int r = 0; r < 4; r++) {
        int kk = ty + 8 * r;
        float xv = tile[kk][tx];
        s0 = fmaf(xv, w0s[kk], s0);
        s1 = fmaf(xv, w1s[kk], s1);
    }
    red0[ty][tx] = s0;
    red1[ty][tx] = s1;
    __syncthreads();
    if (ty == 0) {
        float a0 = 0.f, a1 = 0.f;
        #pragma unroll
        for (int i = 0; i < 8; i++) {
            a0 += red0[i][tx];
            a1 += red1[i][tx];
        }
        g_part[(size_t)(b * TT + t0 + tx) * NKT + kt] = make_float2(a0, a1);
    }
}

__global__ void extra_reduce(const float* __restrict__ bp) {
    int idx = blockIdx.x * 256 + threadIdx.x;      // b*TT + t
    if (idx >= MTOT) return;
    const float2* p = &g_part[(size_t)idx * NKT];
    float a0 = 0.f, a1 = 0.f;
    #pragma unroll
    for (int i = 0; i < NKT; i++) {
        float2 v = p[i];
        a0 += v.x;
        a1 += v.y;
    }
    const float PI_F = 3.14159265358979323846f;
    size_t row = (size_t)idx * NBP;
    g_frq[row + 511] = fminf(fmaxf(a0 + bp[511], -PI_F), PI_F);
    g_frq[row + 512] = fminf(fmaxf(a1 + bp[512], -PI_F), PI_F);
}

__global__ void split_w_kernel(const float* __restrict__ Wm,
                               const float* __restrict__ Wp) {
    int n = blockIdx.x;
    const float* src = (n < NBINS) ? Wm + (size_t)n * DIMK
                                   : Wp + (size_t)(n - NBINS) * DIMK;
    for (int k = threadIdx.x; k < DIMK; k += 256) {
        float v = src[k];
        __nv_bfloat16 h0, h1;
        split2(v, h0, h1);
        size_t o = (size_t)n * DIMK + k;
        g_B[o] = h0;
        g_B[BSZ + o] = h1;
    }
}

// ---------------- HMMA 2-split dual GEMM: 256x128, KC=64, 2-stage (R8 config) -------
__global__ void __launch_bounds__(NTHR, 1) gemm_hmma(
    const float* __restrict__ bmag, const float* __restrict__ bphs)
{
    extern __shared__ char smraw[];
    uint32_t smem_base = smem_u32(smraw);

    int tid = threadIdx.x;
    int lane = tid & 31, wid = tid >> 5;     // 16 warps: 4x4, 64m x 32n each
    int wm = wid >> 2, wn = wid & 3;
    int n0 = blockIdx.x * TLN;
    int m0 = blockIdx.y * TLM;

    float acc[4][4][4];
    #pragma unroll
    for (int mt = 0; mt < 4; mt++)
        #pragma unroll
        for (int nt = 0; nt < 4; nt++)
            #pragma unroll
            for (int r = 0; r < 4; r++) acc[mt][nt][r] = 0.f;

    uint32_t aoff = (uint32_t)((wm * 64 + (lane & 15)) * SROW + (lane >> 4) * 16);
    uint32_t boff = (uint32_t)((wn * 32 + (lane & 7) + (lane >> 4) * 8) * SROW +
                               ((lane >> 3) & 1) * 16);

    // 6144 cp16 per chunk -> 12 per thread -> 4 parts of 3
    #define ISSUE_PART(k0_, buf_, part_) do {                                         \
        uint32_t stage_ = smem_base + (uint32_t)(buf_) * STAGE_BYTES;                 \
        _Pragma("unroll")                                                             \
        for (int j_ = 0; j_ < 3; j_++) {                                              \
            int v_ = tid + ((part_) * 3 + j_) * NTHR;                                 \
            int isB_ = v_ >= 4096;                                                    \
            int r_ = isB_ ? v_ - 4096 : v_;                                           \
            int p_ = isB_ ? (r_ >> 10) : (r_ >> 11);                                  \
            int rem_ = isB_ ? (r_ & 1023) : (r_ & 2047);                              \
            int row_ = rem_ >> 3;                                                     \
            int ch_ = rem_ & 7;                                                       \
            const __nv_bfloat16* s_ = isB_                                            \
                ? g_B + (size_t)p_ * BSZ + (size_t)(n0 + row_) * DIMK + (k0_) + ch_ * 8 \
                : g_A + (size_t)p_ * ASZ + (size_t)(m0 + row_) * DIMK + (k0_) + ch_ * 8; \
            uint32_t d_ = stage_ +                                                    \
                (isB_ ? (uint32_t)(B_BASE + p_ * B_SPLIT) : (uint32_t)(p_ * A_SPLIT)) \
                + (uint32_t)(row_ * SROW + ch_ * 16);                                 \
            cp16(d_, s_);                                                             \
        }                                                                             \
    } while (0)

    // prologue: chunk 0 -> buf 0
    ISSUE_PART(0, 0, 0);
    ISSUE_PART(0, 0, 1);
    ISSUE_PART(0, 0, 2);
    ISSUE_PART(0, 0, 3);
    CP_COMMIT();

    #pragma unroll 1
    for (int c = 0; c < NCHG; c++) {
        int s = c & 1;
        CP_WAIT0();
        __syncthreads();

        uint32_t sA = smem_base + (uint32_t)s * STAGE_BYTES;
        uint32_t sB = sA + B_BASE;
        int knext = (c + 1) * KC;
        bool more = (c + 1 < NCHG);

        #pragma unroll
        for (int ks = 0; ks < 4; ks++) {
            uint32_t afr[4][4];
            uint32_t bfr0[4][2], bfr1[4][2];

            // B fragments, both splits
            {
                uint32_t bd0 = sB + boff + (uint32_t)(ks * 32);
                ldsm_x4(bfr0[0][0], bfr0[0][1], bfr0[1][0], bfr0[1][1], bd0);
                ldsm_x4(bfr0[2][0], bfr0[2][1], bfr0[3][0], bfr0[3][1], bd0 + 16 * SROW);
                uint32_t bd1 = bd0 + B_SPLIT;
                ldsm_x4(bfr1[0][0], bfr1[0][1], bfr1[1][0], bfr1[1][1], bd1);
                ldsm_x4(bfr1[2][0], bfr1[2][1], bfr1[3][0], bfr1[3][1], bd1 + 16 * SROW);
            }
            // A split 0
            #pragma unroll
            for (int mt = 0; mt < 4; mt++) {
                uint32_t ad = sA + aoff + (uint32_t)(mt * 16 * SROW + ks * 32);
                ldsm_x4(afr[mt][0], afr[mt][1], afr[mt][2], afr[mt][3], ad);
            }

            // front-loaded prefetch of next chunk: parts 0,1 at ks0; 2 at ks1;
            // 3 + commit at ks2 -> full kstep (~1500cyc) before next wait
            if (more && ks == 0) ISSUE_PART(knext, s ^ 1, 0);

            #pragma unroll
            for (int mt = 0; mt < 4; mt++)
                #pragma unroll
                for (int nt = 0; nt < 4; nt++)
                    mma_bf16(acc[mt][nt], afr[mt], bfr0[nt]);   // A0*B0

            if (more) {
                if (ks == 0)      ISSUE_PART(knext, s ^ 1, 1);
                else if (ks == 1) ISSUE_PART(knext, s ^ 1, 2);
                else if (ks == 2) ISSUE_PART(knext, s ^ 1, 3);
            }

            #pragma unroll
            for (int mt = 0; mt < 4; mt++)
                #pragma unroll
                for (int nt = 0; nt < 4; nt++)
                    mma_bf16(acc[mt][nt], afr[mt], bfr1[nt]);   // A0*B1

            if (more && ks == 2) CP_COMMIT();

            // A split 1 (reuse afr regs)
            #pragma unroll
            for (int mt = 0; mt < 4; mt++) {
                uint32_t ad = sA + A_SPLIT + aoff + (uint32_t)(mt * 16 * SROW + ks * 32);
                ldsm_x4(afr[mt][0], afr[mt][1], afr[mt][2], afr[mt][3], ad);
            }
            #pragma unroll
            for (int mt = 0; mt < 4; mt++)
                #pragma unroll
                for (int nt = 0; nt < 4; nt++)
                    mma_bf16(acc[mt][nt], afr[mt], bfr0[nt]);   // A1*B0
        }
    }
    #undef ISSUE_PART

    // epilogue
    const float PI_F = 3.14159265358979323846f;
    #pragma unroll
    for (int mt = 0; mt < 4; mt++) {
        #pragma unroll
        for (int nt = 0; nt < 4; nt++) {
            int r0 = m0 + wm * 64 + mt * 16 + (lane >> 2);
            int cg = n0 + wn * 32 + nt * 8 + (lane & 3) * 2;
            #pragma unroll
            for (int hh = 0; hh < 2; hh++) {
                int m = r0 + hh * 8;
                size_t row = (size_t)m * NBP;
                #pragma unroll
                for (int e = 0; e < 2; e++) {
                    int ng = cg + e;
                    float v = acc[mt][nt][hh * 2 + e];
                    if (ng < NBINS) {
                        v += __ldg(bmag + ng);
                        v = fminf(fmaxf(v, -10.f), 10.f);
                        g_mag[row + ng] = __float2half(expf(v));
                    } else {
                        int nn = ng - NBINS;     // phase bins 0..510
                        v += __ldg(bphs + nn);
                        v = fminf(fmaxf(v, -PI_F), PI_F);
                        g_frq[row + nn] = v;
                    }
                }
            }
        }
    }
}

// ---------------- cumsum: seg sums, scan, then fused apply+spectrum --------------------
__global__ void cumsum_seg() {
    int n = blockIdx.x * 128 + threadIdx.x;
    int b = blockIdx.y, sg = blockIdx.z;
    if (n >= NBINS) return;
    size_t base = ((size_t)b * TT + (size_t)sg * TSEG) * NBP + n;
    float acc = 0.f;
    #pragma unroll 8
    for (int t = 0; t < TSEG; t++)
        acc += g_frq[base + (size_t)t * NBP];
    g_segsum[b][sg][n] = acc;
}

__global__ void cumsum_scan() {
    int n = blockIdx.x * 128 + threadIdx.x;
    int b = blockIdx.y;
    if (n >= NBINS) return;
    float acc = 0.f;
    #pragma unroll
    for (int sg = 0; sg < NSEG; sg++) {
        float v = g_segsum[b][sg][n];
        g_segsum[b][sg][n] = acc;    // exclusive prefix
        acc += v;
    }
}

// apply running phase AND build half-spectrum: spec = mag * e^{i phase} (fp16 pair)
__global__ void cumsum_apply() {
    int n = blockIdx.x * 128 + threadIdx.x;
    int b = blockIdx.y, sg = blockIdx.z;
    if (n >= NBINS) return;
    float acc = g_segsum[b][sg][n];
    bool zim = (n == 0 || n == 512);    // real DC/Nyquist (irfft semantics)
    size_t base = ((size_t)b * TT + (size_t)sg * TSEG) * NBP + n;
    #pragma unroll 4
    for (int t = 0; t < TSEG; t++) {
        size_t o = base + (size_t)t * NBP;
        acc += g_frq[o];
        float mg = __half2float(g_mag[o]);
        float s, c;
        __sincosf(acc, &s, &c);
        float im = zim ? 0.f : (mg * s);
        g_spec[o] = __floats2half2_rn(mg * c, im);
    }
}

// ---------------- frames: real irfft(1024) via 512-pt radix-8 complex IFFT -------------
// 2 frames per 128-thread block; 64 threads per frame, each owning a closed
// 8-point group per radix-8 triple (3 triples: stages t=1,4,7).
// Anti-conflict swizzle: phys(k) = k + (k>>3).
#define FPB 2
__device__ __forceinline__ int swz(int k) { return k + (k >> 3); }

__global__ __launch_bounds__(128) void frames_kernel() {
    __shared__ float sxr[FPB][513];
    __shared__ float sxi[FPB][513];
    __shared__ float wre[FPB][576];
    __shared__ float wim[FPB][576];
    __shared__ float twr[256];
    __shared__ float twi[256];

    int tid = threadIdx.x;
    int fl = tid >> 6;
    int u  = tid & 63;
    int f = blockIdx.x * FPB + fl;
    size_t base = (size_t)f * NBP;

    for (int i = tid; i < 256; i += 128) {
        twr[i] = g_c512[i];
        twi[i] = g_s512[i];
    }
    for (int n = u; n < 513; n += 64) {
        float2 v = __half22float2(g_spec[base + n]);
        sxr[fl][n] = v.x;
        sxi[fl][n] = v.y;
    }
    __syncthreads();

    // build G in bit-reversed order (swizzled storage):
    // G[j] = (X[j]+conj(X[512-j])) + i * e^{2pi i j/1024} * (X[j]-conj(X[512-j]))
    #pragma unroll
    for (int q = 0; q < 8; q++) {
        int k = u + q * 64;
        int j = __brev((unsigned)k) >> 23;
        float x0r = sxr[fl][j],       x0i = sxi[fl][j];
        float x1r = sxr[fl][512 - j], x1i = sxi[fl][512 - j];
        float ar = x0r + x1r, ai = x0i - x1i;
        float br = x0r - x1r, bi = x0i + x1i;
        float tr = g_c1024[j], ti = g_s1024[j];
        int kp = swz(k);
        wre[fl][kp] = ar - (tr * bi + ti * br);
        wim[fl][kp] = ai + (tr * br - ti * bi);
    }
    __syncthreads();

    const float S2 = 0.70710678118654752f;
    size_t ob = (size_t)f * NFFT;
    float zr[8], zi[8];

    #pragma unroll
    for (int tt = 0; tt < 3; tt++) {
        const int t = 1 + 3 * tt;           // stage base: 1, 4, 7
        const int h = 1 << (t - 1);         // 1, 8, 64
        int r = u & (h - 1);
        int bi_ = ((u >> (t - 1)) << (t + 2)) | r;
        int k1 = r << (9 - t);

        #pragma unroll
        for (int j = 0; j < 8; j++) {
            int kp = swz(bi_ + j * h);
            zr[j] = wre[fl][kp];
            zi[j] = wim[fl][kp];
        }

        // level 1: pairs (j, j+1), twiddle W^k1
        float w1r = twr[k1], w1i = twi[k1];
        #pragma unroll
        for (int q = 0; q < 8; q += 2) {
            float tr_ = zr[q + 1] * w1r - zi[q + 1] * w1i;
            float ti_ = zr[q + 1] * w1i + zi[q + 1] * w1r;
            zr[q + 1] = zr[q] - tr_;  zi[q + 1] = zi[q] - ti_;
            zr[q] += tr_;             zi[q] += ti_;
        }
        // level 2: pairs (g,g+2),(g+1,g+3), twiddles W^(k1/2), i*W^(k1/2)
        float w2r = twr[k1 >> 1], w2i = twi[k1 >> 1];
        #pragma unroll
        for (int g = 0; g < 8; g += 4) {
            float tr0 = zr[g + 2] * w2r - zi[g + 2] * w2i;
            float ti0 = zr[g + 2] * w2i + zi[g + 2] * w2r;
            zr[g + 2] = zr[g] - tr0;  zi[g + 2] = zi[g] - ti0;
            zr[g] += tr0;             zi[g] += ti0;
            float cr = zr[g + 3] * w2r - zi[g + 3] * w2i;
            float ci = zr[g + 3] * w2i + zi[g + 3] * w2r;
            float tr1 = -ci, ti1 = cr;              // * (+i)
            zr[g + 3] = zr[g + 1] - tr1;  zi[g + 3] = zi[g + 1] - ti1;
            zr[g + 1] += tr1;             zi[g + 1] += ti1;
        }
        // level 3: pairs (j, j+4), twiddles W^(k1/4) * e^{i pi j/4}
        float w3r = twr[k1 >> 2], w3i = twi[k1 >> 2];
        float fr[4], fi[4];
        fr[0] = w3r;                 fi[0] = w3i;
        fr[1] = S2 * (w3r - w3i);    fi[1] = S2 * (w3r + w3i);
        fr[2] = -w3i;                fi[2] = w3r;
        fr[3] = -S2 * (w3r + w3i);   fi[3] = S2 * (w3r - w3i);
        #pragma unroll
        for (int j = 0; j < 4; j++) {
            float tr_ = zr[j + 4] * fr[j] - zi[j + 4] * fi[j];
            float ti_ = zr[j + 4] * fi[j] + zi[j + 4] * fr[j];
            zr[j + 4] = zr[j] - tr_;  zi[j + 4] = zi[j] - ti_;
            zr[j] += tr_;             zi[j] += ti_;
        }

        if (tt < 2) {
            #pragma unroll
            for (int j = 0; j < 8; j++) {
                int kp = swz(bi_ + j * h);
                wre[fl][kp] = zr[j];
                wim[fl][kp] = zi[j];
            }
            __syncthreads();
        } else {
            // natural order output: z[j] at position u + 64j
            // x[2m] = Re z[m], x[2m+1] = Im z[m], windowed, stored fp16
            #pragma unroll
            for (int j = 0; j < 8; j++) {
                int m = u + 64 * j;
                float2 o = make_float2(zr[j] * g_winS[2 * m],
                                       zi[j] * g_winS[2 * m + 1]);
                *reinterpret_cast<__half2*>(&g_frames[ob + 2 * m]) =
                    __float22half2_rn(o);
            }
        }
    }
}

// ---------------- overlap-add (4 samples per thread, fp16 frames) ----------------------
__global__ void oa_kernel(float* __restrict__ out) {
    int idx4 = blockIdx.x * 256 + threadIdx.x;
    const int GROUPS = OUTLEN / 4;           // 131008
    if (idx4 >= BATCH * GROUPS) return;
    int b = idx4 / GROUPS;
    int s = (idx4 - b * GROUPS) * 4;
    int p = s + NFFT / 2;                    // 4-aligned; group never straddles frames

    int t1 = p >> 8;  if (t1 > TT - 1) t1 = TT - 1;
    int t0 = (p >= NFFT - HOP) ? ((p - (NFFT - HOP)) >> 8) : 0;

    float4 sig = make_float4(0.f, 0.f, 0.f, 0.f);
    float4 env = make_float4(0.f, 0.f, 0.f, 0.f);
    #pragma unroll 4
    for (int t = t0; t <= t1; t++) {
        int j = p - (t << 8);
        const __half2* fp = reinterpret_cast<const __half2*>(
            &g_frames[((size_t)(b * TT + t) << 10) + j]);
        float2 f0 = __half22float2(fp[0]);
        float2 f1 = __half22float2(fp[1]);
        float4 wv = *reinterpret_cast<const float4*>(&g_win2[j]);
        sig.x += f0.x; sig.y += f0.y; sig.z += f1.x; sig.w += f1.y;
        env.x += wv.x; env.y += wv.y; env.z += wv.z; env.w += wv.w;
    }
    float4 o;
    o.x = fminf(fmaxf(sig.x / env.x, -1.f), 1.f);
    o.y = fminf(fmaxf(sig.y / env.y, -1.f), 1.f);
    o.z = fminf(fmaxf(sig.z / env.z, -1.f), 1.f);
    o.w = fminf(fmaxf(sig.w / env.w, -1.f), 1.f);
    *reinterpret_cast<float4*>(&out[(size_t)b * OUTLEN + s]) = o;
}

// ---------------- launcher ----------------------------------------------------------------
extern "C" void kernel_launch(void* const* d_in, const int* in_sizes, int n_in,
                              void* d_out, int out_size) {
    (void)in_sizes; (void)n_in; (void)out_size;
    const float* x  = (const float*)d_in[0];
    const float* Wm = (const float*)d_in[1];
    const float* bm = (const float*)d_in[2];
    const float* Wp = (const float*)d_in[3];
    const float* bp = (const float*)d_in[4];
    float* out = (float*)d_out;

    cudaFuncSetAttribute(gemm_hmma, cudaFuncAttributeMaxDynamicSharedMemorySize,
                         GEMM_SMEM);

    init_tables<<<4, 256>>>();
    split_x_kernel<<<dim3(TT / 32, DIMK / 32, BATCH), dim3(32, 8)>>>(x, Wp);
    split_w_kernel<<<NPAD, 256>>>(Wm, Wp);

    gemm_hmma<<<dim3(NPAD / TLN, MTOT / TLM), NTHR, GEMM_SMEM>>>(bm, bp);
    extra_reduce<<<MTOT / 256, 256>>>(bp);

    cumsum_seg<<<dim3(5, BATCH, NSEG), 128>>>();
    cumsum_scan<<<dim3(5, BATCH), 128>>>();
    cumsum_apply<<<dim3(5, BATCH, NSEG), 128>>>();

    frames_kernel<<<MTOT / FPB, 128>>>();
    oa_kernel<<<(BATCH * (OUTLEN / 4) + 255) / 256, 256>>>(out);
}

// round 16
// speedup vs baseline: 1.0571x; 1.0571x over previous
#include <cuda_runtime.h>
#include <cuda_bf16.h>
#include <cuda_fp16.h>
#include <math.h>
#include <cstdint>

#define BATCH 16
#define DIMK  1024
#define TT    2048
#define NFFT  1024
#define HOP   256
#define NBINS 513
#define NBP   520
#define MTOT  (BATCH * TT)          // 32768
#define OUTLEN (HOP * (TT - 1))     // 524032

#define NPAD  1024                  // 8 n-tiles; bins 511/512 (phase) via split_x path
#define TLM   256
#define TLN   128
#define KC    64
#define NCHG  (DIMK / KC)           // 16
#define NSPLIT 2
#define NTHR  512

#define TSEG  128
#define NSEG  (TT / TSEG)           // 16
#define NKT   (DIMK / 32)           // 32 k-tiles in split_x

static constexpr size_t ASZ = (size_t)MTOT * DIMK;
static constexpr size_t BSZ = (size_t)NPAD * DIMK;

// smem: rows of 128B data + 16B pad (conflict-free: 144 mod 128 = 16)
#define SROW        144
#define A_SPLIT     (256 * SROW)              // 36864
#define B_SPLIT     (128 * SROW)              // 18432
#define B_BASE      (2 * A_SPLIT)             // 73728
#define STAGE_BYTES (2 * A_SPLIT + 2 * B_SPLIT)  // 110592
#define NSTAGE      2
#define GEMM_SMEM   (NSTAGE * STAGE_BYTES)    // 221184

// ---------------- scratch ----------------------------------------------------
__device__ __nv_bfloat16 g_A[(size_t)NSPLIT * ASZ];
__device__ __nv_bfloat16 g_B[(size_t)NSPLIT * BSZ];
__device__ __half g_mag[(size_t)MTOT * NBP];
__device__ float g_frq[(size_t)MTOT * NBP];
__device__ __half g_frames[(size_t)MTOT * NFFT];
__device__ float2 g_part[(size_t)MTOT * NKT];     // partial dots for bins 511/512
__device__ float g_segsum[BATCH][NSEG][NBP];
__device__ float g_c1024[512];
__device__ float g_s1024[512];
__device__ float g_c512[256];
__device__ float g_s512[256];
__device__ float g_winS[1024];
__device__ float g_win2[1024];

// ---------------- helpers -----------------------------------------------------
__device__ __forceinline__ uint32_t smem_u32(const void* p) {
    uint32_t a;
    asm("{ .reg .u64 t; cvta.to.shared.u64 t, %1; cvt.u32.u64 %0, t; }"
        : "=r"(a) : "l"(p));
    return a;
}
__device__ __forceinline__ void cp16(uint32_t dst, const void* src) {
    asm volatile("cp.async.cg.shared.global [%0], [%1], 16;" :: "r"(dst), "l"(src));
}
#define CP_COMMIT() asm volatile("cp.async.commit_group;")
#define CP_WAIT0()  asm volatile("cp.async.wait_group 0;" ::: "memory")

__device__ __forceinline__ void ldsm_x4(uint32_t& r0, uint32_t& r1,
                                        uint32_t& r2, uint32_t& r3, uint32_t a) {
    asm volatile("ldmatrix.sync.aligned.m8n8.x4.shared.b16 {%0,%1,%2,%3}, [%4];"
                 : "=r"(r0), "=r"(r1), "=r"(r2), "=r"(r3) : "r"(a));
}
__device__ __forceinline__ void mma_bf16(float* c, const uint32_t* a, const uint32_t* b) {
    asm volatile(
        "mma.sync.aligned.m16n8k16.row.col.f32.bf16.bf16.f32 "
        "{%0,%1,%2,%3}, {%4,%5,%6,%7}, {%8,%9}, {%0,%1,%2,%3};"
        : "+f"(c[0]), "+f"(c[1]), "+f"(c[2]), "+f"(c[3])
        : "r"(a[0]), "r"(a[1]), "r"(a[2]), "r"(a[3]), "r"(b[0]), "r"(b[1]));
}

// ---------------- table init ---------------------------------------------------
__global__ void init_tables() {
    int i = blockIdx.x * blockDim.x + threadIdx.x;
    const float TWO_PI = 6.283185307179586f;
    if (i < 512) {
        float a = TWO_PI * (float)i / 1024.0f;
        g_c1024[i] = cosf(a);
        g_s1024[i] = sinf(a);
    }
    if (i < 256) {
        float a = TWO_PI * (float)i / 512.0f;
        g_c512[i] = cosf(a);
        g_s512[i] = sinf(a);
    }
    if (i < 1024) {
        float w = 0.5f * (1.0f - cosf(TWO_PI * (float)i / 1024.0f));
        g_winS[i] = w * (1.0f / 1024.0f);
        g_win2[i] = w * w;
    }
}

// ---------------- split prep (2 terms) + extra-bin partial dots ---------------------
__device__ __forceinline__ void split2(float v, __nv_bfloat16& h0, __nv_bfloat16& h1) {
    h0 = __float2bfloat16(v);
    h1 = __float2bfloat16(v - __bfloat162float(h0));
}

__global__ void split_x_kernel(const float* __restrict__ x,
                               const float* __restrict__ Wp) {
    __shared__ float tile[32][33];
    __shared__ float w0s[32], w1s[32];
    __shared__ float red0[8][32];
    __shared__ float red1[8][32];
    int b = blockIdx.z;
    int kt = blockIdx.y;
    int k0 = kt * 32, t0 = blockIdx.x * 32;
    int tx = threadIdx.x, ty = threadIdx.y;

    if (ty == 0) {
        w0s[tx] = Wp[(size_t)511 * DIMK + k0 + tx];
        w1s[tx] = Wp[(size_t)512 * DIMK + k0 + tx];
    }
    const float* src = x + ((size_t)b * DIMK + k0) * TT + t0;
    #pragma unroll
    for (int r = 0; r < 4; r++)
        tile[ty + 8 * r][tx] = src[(size_t)(ty + 8 * r) * TT + tx];
    __syncthreads();

    // bf16 splits (transposed read)
    #pragma unroll
    for (int r = 0; r < 4; r++) {
        float v = tile[tx][ty + 8 * r];
        size_t m = (size_t)b * TT + t0 + ty + 8 * r;
        __nv_bfloat16 h0, h1;
        split2(v, h0, h1);
        size_t o = m * DIMK + k0 + tx;
        g_A[o] = h0;
        g_A[ASZ + o] = h1;
    }

    // partial dots for phase bins 511/512 (thread owns t=t0+tx, 4 k-values)
    float s0 = 0.f, s1 = 0.f;
    #pragma unroll
    for (int r = 0; r < 4; r++) {
        int kk = ty + 8 * r;
        float xv = tile[kk][tx];
        s0 = fmaf(xv, w0s[kk], s0);
        s1 = fmaf(xv, w1s[kk], s1);
    }
    red0[ty][tx] = s0;
    red1[ty][tx] = s1;
    __syncthreads();
    if (ty == 0) {
        float a0 = 0.f, a1 = 0.f;
        #pragma unroll
        for (int i = 0; i < 8; i++) {
            a0 += red0[i][tx];
            a1 += red1[i][tx];
        }
        g_part[(size_t)(b * TT + t0 + tx) * NKT + kt] = make_float2(a0, a1);
    }
}

__global__ void extra_reduce(const float* __restrict__ bp) {
    int idx = blockIdx.x * 256 + threadIdx.x;      // b*TT + t
    if (idx >= MTOT) return;
    const float2* p = &g_part[(size_t)idx * NKT];
    float a0 = 0.f, a1 = 0.f;
    #pragma unroll
    for (int i = 0; i < NKT; i++) {
        float2 v = p[i];
        a0 += v.x;
        a1 += v.y;
    }
    const float PI_F = 3.14159265358979323846f;
    size_t row = (size_t)idx * NBP;
    g_frq[row + 511] = fminf(fmaxf(a0 + bp[511], -PI_F), PI_F);
    g_frq[row + 512] = fminf(fmaxf(a1 + bp[512], -PI_F), PI_F);
}

__global__ void split_w_kernel(const float* __restrict__ Wm,
                               const float* __restrict__ Wp) {
    int n = blockIdx.x;
    const float* src = (n < NBINS) ? Wm + (size_t)n * DIMK
                                   : Wp + (size_t)(n - NBINS) * DIMK;
    for (int k = threadIdx.x; k < DIMK; k += 256) {
        float v = src[k];
        __nv_bfloat16 h0, h1;
        split2(v, h0, h1);
        size_t o = (size_t)n * DIMK + k;
        g_B[o] = h0;
        g_B[BSZ + o] = h1;
    }
}

// ---------------- HMMA 2-split dual GEMM: 256x128, KC=64, 2-stage (R8 config) -------
__global__ void __launch_bounds__(NTHR, 1) gemm_hmma(
    const float* __restrict__ bmag, const float* __restrict__ bphs)
{
    extern __shared__ char smraw[];
    uint32_t smem_base = smem_u32(smraw);

    int tid = threadIdx.x;
    int lane = tid & 31, wid = tid >> 5;     // 16 warps: 4x4, 64m x 32n each
    int wm = wid >> 2, wn = wid & 3;
    int n0 = blockIdx.x * TLN;
    int m0 = blockIdx.y * TLM;

    float acc[4][4][4];
    #pragma unroll
    for (int mt = 0; mt < 4; mt++)
        #pragma unroll
        for (int nt = 0; nt < 4; nt++)
            #pragma unroll
            for (int r = 0; r < 4; r++) acc[mt][nt][r] = 0.f;

    uint32_t aoff = (uint32_t)((wm * 64 + (lane & 15)) * SROW + (lane >> 4) * 16);
    uint32_t boff = (uint32_t)((wn * 32 + (lane & 7) + (lane >> 4) * 8) * SROW +
                               ((lane >> 3) & 1) * 16);

    // 6144 cp16 per chunk -> 12 per thread -> 4 parts of 3
    #define ISSUE_PART(k0_, buf_, part_) do {                                         \
        uint32_t stage_ = smem_base + (uint32_t)(buf_) * STAGE_BYTES;                 \
        _Pragma("unroll")                                                             \
        for (int j_ = 0; j_ < 3; j_++) {                                              \
            int v_ = tid + ((part_) * 3 + j_) * NTHR;                                 \
            int isB_ = v_ >= 4096;                                                    \
            int r_ = isB_ ? v_ - 4096 : v_;                                           \
            int p_ = isB_ ? (r_ >> 10) : (r_ >> 11);                                  \
            int rem_ = isB_ ? (r_ & 1023) : (r_ & 2047);                              \
            int row_ = rem_ >> 3;                                                     \
            int ch_ = rem_ & 7;                                                       \
            const __nv_bfloat16* s_ = isB_                                            \
                ? g_B + (size_t)p_ * BSZ + (size_t)(n0 + row_) * DIMK + (k0_) + ch_ * 8 \
                : g_A + (size_t)p_ * ASZ + (size_t)(m0 + row_) * DIMK + (k0_) + ch_ * 8; \
            uint32_t d_ = stage_ +                                                    \
                (isB_ ? (uint32_t)(B_BASE + p_ * B_SPLIT) : (uint32_t)(p_ * A_SPLIT)) \
                + (uint32_t)(row_ * SROW + ch_ * 16);                                 \
            cp16(d_, s_);                                                             \
        }                                                                             \
    } while (0)

    // prologue: chunk 0 -> buf 0
    ISSUE_PART(0, 0, 0);
    ISSUE_PART(0, 0, 1);
    ISSUE_PART(0, 0, 2);
    ISSUE_PART(0, 0, 3);
    CP_COMMIT();

    #pragma unroll 1
    for (int c = 0; c < NCHG; c++) {
        int s = c & 1;
        CP_WAIT0();
        __syncthreads();

        uint32_t sA = smem_base + (uint32_t)s * STAGE_BYTES;
        uint32_t sB = sA + B_BASE;
        int knext = (c + 1) * KC;
        bool more = (c + 1 < NCHG);

        #pragma unroll
        for (int ks = 0; ks < 4; ks++) {
            uint32_t afr[4][4];
            uint32_t bfr0[4][2], bfr1[4][2];

            // B fragments, both splits
            {
                uint32_t bd0 = sB + boff + (uint32_t)(ks * 32);
                ldsm_x4(bfr0[0][0], bfr0[0][1], bfr0[1][0], bfr0[1][1], bd0);
                ldsm_x4(bfr0[2][0], bfr0[2][1], bfr0[3][0], bfr0[3][1], bd0 + 16 * SROW);
                uint32_t bd1 = bd0 + B_SPLIT;
                ldsm_x4(bfr1[0][0], bfr1[0][1], bfr1[1][0], bfr1[1][1], bd1);
                ldsm_x4(bfr1[2][0], bfr1[2][1], bfr1[3][0], bfr1[3][1], bd1 + 16 * SROW);
            }
            // A split 0
            #pragma unroll
            for (int mt = 0; mt < 4; mt++) {
                uint32_t ad = sA + aoff + (uint32_t)(mt * 16 * SROW + ks * 32);
                ldsm_x4(afr[mt][0], afr[mt][1], afr[mt][2], afr[mt][3], ad);
            }

            // front-loaded prefetch of next chunk: parts 0,1 at ks0; 2 at ks1;
            // 3 + commit at ks2 -> full kstep (~1500cyc) before next wait
            if (more && ks == 0) ISSUE_PART(knext, s ^ 1, 0);

            #pragma unroll
            for (int mt = 0; mt < 4; mt++)
                #pragma unroll
                for (int nt = 0; nt < 4; nt++)
                    mma_bf16(acc[mt][nt], afr[mt], bfr0[nt]);   // A0*B0

            if (more) {
                if (ks == 0)      ISSUE_PART(knext, s ^ 1, 1);
                else if (ks == 1) ISSUE_PART(knext, s ^ 1, 2);
                else if (ks == 2) ISSUE_PART(knext, s ^ 1, 3);
            }

            #pragma unroll
            for (int mt = 0; mt < 4; mt++)
                #pragma unroll
                for (int nt = 0; nt < 4; nt++)
                    mma_bf16(acc[mt][nt], afr[mt], bfr1[nt]);   // A0*B1

            if (more && ks == 2) CP_COMMIT();

            // A split 1 (reuse afr regs)
            #pragma unroll
            for (int mt = 0; mt < 4; mt++) {
                uint32_t ad = sA + A_SPLIT + aoff + (uint32_t)(mt * 16 * SROW + ks * 32);
                ldsm_x4(afr[mt][0], afr[mt][1], afr[mt][2], afr[mt][3], ad);
            }
            #pragma unroll
            for (int mt = 0; mt < 4; mt++)
                #pragma unroll
                for (int nt = 0; nt < 4; nt++)
                    mma_bf16(acc[mt][nt], afr[mt], bfr0[nt]);   // A1*B0
        }
    }
    #undef ISSUE_PART

    // epilogue
    const float PI_F = 3.14159265358979323846f;
    #pragma unroll
    for (int mt = 0; mt < 4; mt++) {
        #pragma unroll
        for (int nt = 0; nt < 4; nt++) {
            int r0 = m0 + wm * 64 + mt * 16 + (lane >> 2);
            int cg = n0 + wn * 32 + nt * 8 + (lane & 3) * 2;
            #pragma unroll
            for (int hh = 0; hh < 2; hh++) {
                int m = r0 + hh * 8;
                size_t row = (size_t)m * NBP;
                #pragma unroll
                for (int e = 0; e < 2; e++) {
                    int ng = cg + e;
                    float v = acc[mt][nt][hh * 2 + e];
                    if (ng < NBINS) {
                        v += __ldg(bmag + ng);
                        v = fminf(fmaxf(v, -10.f), 10.f);
                        g_mag[row + ng] = __float2half(__expf(v));
                    } else {
                        int nn = ng - NBINS;     // phase bins 0..510
                        v += __ldg(bphs + nn);
                        v = fminf(fmaxf(v, -PI_F), PI_F);
                        g_frq[row + nn] = v;
                    }
                }
            }
        }
    }
}

// ---------------- cumsum: 3-phase segmented scan (16 segments of 128) -----------------
__global__ void cumsum_seg() {
    int n = blockIdx.x * 128 + threadIdx.x;
    int b = blockIdx.y, sg = blockIdx.z;
    if (n >= NBINS) return;
    size_t base = ((size_t)b * TT + (size_t)sg * TSEG) * NBP + n;
    float acc = 0.f;
    #pragma unroll 8
    for (int t = 0; t < TSEG; t++)
        acc += g_frq[base + (size_t)t * NBP];
    g_segsum[b][sg][n] = acc;
}

__global__ void cumsum_scan() {
    int n = blockIdx.x * 128 + threadIdx.x;
    int b = blockIdx.y;
    if (n >= NBINS) return;
    float acc = 0.f;
    #pragma unroll
    for (int sg = 0; sg < NSEG; sg++) {
        float v = g_segsum[b][sg][n];
        g_segsum[b][sg][n] = acc;    // exclusive prefix
        acc += v;
    }
}

__global__ void cumsum_apply() {
    int n = blockIdx.x * 128 + threadIdx.x;
    int b = blockIdx.y, sg = blockIdx.z;
    if (n >= NBINS) return;
    float acc = g_segsum[b][sg][n];
    size_t base = ((size_t)b * TT + (size_t)sg * TSEG) * NBP + n;
    #pragma unroll 8
    for (int t = 0; t < TSEG; t++) {
        size_t o = base + (size_t)t * NBP;
        acc += g_frq[o];
        g_frq[o] = acc;
    }
}

// ---------------- frames: real irfft(1024) via 512-pt radix-8 complex IFFT -------------
// 2 frames per 128-thread block; 64 threads per frame, each owning a closed
// 8-point group per radix-8 triple (3 triples: stages t=1,4,7).
// Anti-conflict swizzle: phys(k) = k + (k>>3).
#define FPB 2
__device__ __forceinline__ int swz(int k) { return k + (k >> 3); }

__global__ __launch_bounds__(128) void frames_kernel() {
    __shared__ float sxr[FPB][513];
    __shared__ float sxi[FPB][513];
    __shared__ float wre[FPB][576];
    __shared__ float wim[FPB][576];
    __shared__ float twr[256];
    __shared__ float twi[256];

    int tid = threadIdx.x;
    int fl = tid >> 6;
    int u  = tid & 63;
    int f = blockIdx.x * FPB + fl;
    size_t base = (size_t)f * NBP;

    for (int i = tid; i < 256; i += 128) {
        twr[i] = g_c512[i];
        twi[i] = g_s512[i];
    }
    for (int n = u; n < 513; n += 64) {
        float mg = __half2float(g_mag[base + n]);
        float ph = g_frq[base + n];
        float s, c;
        __sincosf(ph, &s, &c);
        float im = mg * s;
        if (n == 0 || n == 512) im = 0.f;   // real DC/Nyquist (irfft semantics)
        sxr[fl][n] = mg * c;
        sxi[fl][n] = im;
    }
    __syncthreads();

    // build G in bit-reversed order (swizzled storage):
    // G[j] = (X[j]+conj(X[512-j])) + i * e^{2pi i j/1024} * (X[j]-conj(X[512-j]))
    #pragma unroll
    for (int q = 0; q < 8; q++) {
        int k = u + q * 64;
        int j = __brev((unsigned)k) >> 23;
        float x0r = sxr[fl][j],       x0i = sxi[fl][j];
        float x1r = sxr[fl][512 - j], x1i = sxi[fl][512 - j];
        float ar = x0r + x1r, ai = x0i - x1i;
        float br = x0r - x1r, bi = x0i + x1i;
        float tr = g_c1024[j], ti = g_s1024[j];
        int kp = swz(k);
        wre[fl][kp] = ar - (tr * bi + ti * br);
        wim[fl][kp] = ai + (tr * br - ti * bi);
    }
    __syncthreads();

    const float S2 = 0.70710678118654752f;
    size_t ob = (size_t)f * NFFT;
    float zr[8], zi[8];

    #pragma unroll
    for (int tt = 0; tt < 3; tt++) {
        const int t = 1 + 3 * tt;           // stage base: 1, 4, 7
        const int h = 1 << (t - 1);         // 1, 8, 64
        int r = u & (h - 1);
        int bi_ = ((u >> (t - 1)) << (t + 2)) | r;
        int k1 = r << (9 - t);

        #pragma unroll
        for (int j = 0; j < 8; j++) {
            int kp = swz(bi_ + j * h);
            zr[j] = wre[fl][kp];
            zi[j] = wim[fl][kp];
        }

        // level 1: pairs (j, j+1), twiddle W^k1
        float w1r = twr[k1], w1i = twi[k1];
        #pragma unroll
        for (int q = 0; q < 8; q += 2) {
            float tr_ = zr[q + 1] * w1r - zi[q + 1] * w1i;
            float ti_ = zr[q + 1] * w1i + zi[q + 1] * w1r;
            zr[q + 1] = zr[q] - tr_;  zi[q + 1] = zi[q] - ti_;
            zr[q] += tr_;             zi[q] += ti_;
        }
        // level 2: pairs (g,g+2),(g+1,g+3), twiddles W^(k1/2), i*W^(k1/2)
        float w2r = twr[k1 >> 1], w2i = twi[k1 >> 1];
        #pragma unroll
        for (int g = 0; g < 8; g += 4) {
            float tr0 = zr[g + 2] * w2r - zi[g + 2] * w2i;
            float ti0 = zr[g + 2] * w2i + zi[g + 2] * w2r;
            zr[g + 2] = zr[g] - tr0;  zi[g + 2] = zi[g] - ti0;
            zr[g] += tr0;             zi[g] += ti0;
            float cr = zr[g + 3] * w2r - zi[g + 3] * w2i;
            float ci = zr[g + 3] * w2i + zi[g + 3] * w2r;
            float tr1 = -ci, ti1 = cr;              // * (+i)
            zr[g + 3] = zr[g + 1] - tr1;  zi[g + 3] = zi[g + 1] - ti1;
            zr[g + 1] += tr1;             zi[g + 1] += ti1;
        }
        // level 3: pairs (j, j+4), twiddles W^(k1/4) * e^{i pi j/4}
        float w3r = twr[k1 >> 2], w3i = twi[k1 >> 2];
        float fr[4], fi[4];
        fr[0] = w3r;                 fi[0] = w3i;
        fr[1] = S2 * (w3r - w3i);    fi[1] = S2 * (w3r + w3i);
        fr[2] = -w3i;                fi[2] = w3r;
        fr[3] = -S2 * (w3r + w3i);   fi[3] = S2 * (w3r - w3i);
        #pragma unroll
        for (int j = 0; j < 4; j++) {
            float tr_ = zr[j + 4] * fr[j] - zi[j + 4] * fi[j];
            float ti_ = zr[j + 4] * fi[j] + zi[j + 4] * fr[j];
            zr[j + 4] = zr[j] - tr_;  zi[j + 4] = zi[j] - ti_;
            zr[j] += tr_;             zi[j] += ti_;
        }

        if (tt < 2) {
            #pragma unroll
            for (int j = 0; j < 8; j++) {
                int kp = swz(bi_ + j * h);
                wre[fl][kp] = zr[j];
                wim[fl][kp] = zi[j];
            }
            __syncthreads();
        } else {
            // natural order output: z[j] at position u + 64j
            // x[2m] = Re z[m], x[2m+1] = Im z[m], windowed, stored fp16
            #pragma unroll
            for (int j = 0; j < 8; j++) {
                int m = u + 64 * j;
                float2 o = make_float2(zr[j] * g_winS[2 * m],
                                       zi[j] * g_winS[2 * m + 1]);
                *reinterpret_cast<__half2*>(&g_frames[ob + 2 * m]) =
                    __float22half2_rn(o);
            }
        }
    }
}

// ---------------- overlap-add (4 samples per thread, fp16 frames) ----------------------
__global__ void oa_kernel(float* __restrict__ out) {
    int idx4 = blockIdx.x * 256 + threadIdx.x;
    const int GROUPS = OUTLEN / 4;           // 131008
    if (idx4 >= BATCH * GROUPS) return;
    int b = idx4 / GROUPS;
    int s = (idx4 - b * GROUPS) * 4;
    int p = s + NFFT / 2;                    // 4-aligned; group never straddles frames

    int t1 = p >> 8;  if (t1 > TT - 1) t1 = TT - 1;
    int t0 = (p >= NFFT - HOP) ? ((p - (NFFT - HOP)) >> 8) : 0;

    float4 sig = make_float4(0.f, 0.f, 0.f, 0.f);
    float4 env = make_float4(0.f, 0.f, 0.f, 0.f);
    #pragma unroll 4
    for (int t = t0; t <= t1; t++) {
        int j = p - (t << 8);
        const __half2* fp = reinterpret_cast<const __half2*>(
            &g_frames[((size_t)(b * TT + t) << 10) + j]);
        float2 f0 = __half22float2(fp[0]);
        float2 f1 = __half22float2(fp[1]);
        float4 wv = *reinterpret_cast<const float4*>(&g_win2[j]);
        sig.x += f0.x; sig.y += f0.y; sig.z += f1.x; sig.w += f1.y;
        env.x += wv.x; env.y += wv.y; env.z += wv.z; env.w += wv.w;
    }
    float4 o;
    o.x = fminf(fmaxf(sig.x / env.x, -1.f), 1.f);
    o.y = fminf(fmaxf(sig.y / env.y, -1.f), 1.f);
    o.z = fminf(fmaxf(sig.z / env.z, -1.f), 1.f);
    o.w = fminf(fmaxf(sig.w / env.w, -1.f), 1.f);
    *reinterpret_cast<float4*>(&out[(size_t)b * OUTLEN + s]) = o;
}

// ---------------- launcher ----------------------------------------------------------------
extern "C" void kernel_launch(void* const* d_in, const int* in_sizes, int n_in,
                              void* d_out, int out_size) {
    (void)in_sizes; (void)n_in; (void)out_size;
    const float* x  = (const float*)d_in[0];
    const float* Wm = (const float*)d_in[1];
    const float* bm = (const float*)d_in[2];
    const float* Wp = (const float*)d_in[3];
    const float* bp = (const float*)d_in[4];
    float* out = (float*)d_out;

    cudaFuncSetAttribute(gemm_hmma, cudaFuncAttributeMaxDynamicSharedMemorySize,
                         GEMM_SMEM);

    init_tables<<<4, 256>>>();
    split_x_kernel<<<dim3(TT / 32, DIMK / 32, BATCH), dim3(32, 8)>>>(x, Wp);
    split_w_kernel<<<NPAD, 256>>>(Wm, Wp);

    gemm_hmma<<<dim3(NPAD / TLN, MTOT / TLM), NTHR, GEMM_SMEM>>>(bm, bp);
    extra_reduce<<<MTOT / 256, 256>>>(bp);

    cumsum_seg<<<dim3(5, BATCH, NSEG), 128>>>();
    cumsum_scan<<<dim3(5, BATCH), 128>>>();
    cumsum_apply<<<dim3(5, BATCH, NSEG), 128>>>();

    frames_kernel<<<MTOT / FPB, 128>>>();
    oa_kernel<<<(BATCH * (OUTLEN / 4) + 255) / 256, 256>>>(out);
}

// round 17
// speedup vs baseline: 1.0575x; 1.0004x over previous
#include <cuda_runtime.h>
#include <cuda_bf16.h>
#include <cuda_fp16.h>
#include <math.h>
#include <cstdint>

#define BATCH 16
#define DIMK  1024
#define TT    2048
#define NFFT  1024
#define HOP   256
#define NBINS 513
#define NBP   520
#define MTOT  (BATCH * TT)          // 32768
#define OUTLEN (HOP * (TT - 1))     // 524032

#define NPAD  1024                  // 8 n-tiles; bins 511/512 (phase) via split_x path
#define TLM   256
#define TLN   128
#define KC    64
#define NCHG  (DIMK / KC)           // 16
#define NSPLIT 2
#define NTHR  512

#define TSEG  128
#define NSEG  (TT / TSEG)           // 16
#define NKT   (DIMK / 32)           // 32 k-tiles in split_x

static constexpr size_t ASZ = (size_t)MTOT * DIMK;
static constexpr size_t BSZ = (size_t)NPAD * DIMK;

// smem: rows of 128B data + 16B pad (conflict-free: 144 mod 128 = 16)
#define SROW        144
#define A_SPLIT     (256 * SROW)              // 36864
#define B_SPLIT     (128 * SROW)              // 18432
#define B_BASE      (2 * A_SPLIT)             // 73728
#define STAGE_BYTES (2 * A_SPLIT + 2 * B_SPLIT)  // 110592
#define NSTAGE      2
#define GEMM_SMEM   (NSTAGE * STAGE_BYTES)    // 221184

// ---------------- scratch ----------------------------------------------------
__device__ __nv_bfloat16 g_A[(size_t)NSPLIT * ASZ];
__device__ __nv_bfloat16 g_B[(size_t)NSPLIT * BSZ];
__device__ __half g_mag[(size_t)MTOT * NBP];
__device__ float g_frq[(size_t)MTOT * NBP];
__device__ __half g_frames[(size_t)MTOT * NFFT];
__device__ float2 g_part[(size_t)MTOT * NKT];     // partial dots for bins 511/512
__device__ float g_segsum[BATCH][NSEG][NBP];
__device__ float g_c1024[512];
__device__ float g_s1024[512];
__device__ float g_c512[256];
__device__ float g_s512[256];
__device__ float g_winS[1024];
__device__ float g_win2[1024];

// ---------------- helpers -----------------------------------------------------
__device__ __forceinline__ uint32_t smem_u32(const void* p) {
    uint32_t a;
    asm("{ .reg .u64 t; cvta.to.shared.u64 t, %1; cvt.u32.u64 %0, t; }"
        : "=r"(a) : "l"(p));
    return a;
}
__device__ __forceinline__ void cp16(uint32_t dst, const void* src) {
    asm volatile("cp.async.cg.shared.global [%0], [%1], 16;" :: "r"(dst), "l"(src));
}
#define CP_COMMIT() asm volatile("cp.async.commit_group;")
#define CP_WAIT0()  asm volatile("cp.async.wait_group 0;" ::: "memory")

__device__ __forceinline__ void ldsm_x4(uint32_t& r0, uint32_t& r1,
                                        uint32_t& r2, uint32_t& r3, uint32_t a) {
    asm volatile("ldmatrix.sync.aligned.m8n8.x4.shared.b16 {%0,%1,%2,%3}, [%4];"
                 : "=r"(r0), "=r"(r1), "=r"(r2), "=r"(r3) : "r"(a));
}
__device__ __forceinline__ void mma_bf16(float* c, const uint32_t* a, const uint32_t* b) {
    asm volatile(
        "mma.sync.aligned.m16n8k16.row.col.f32.bf16.bf16.f32 "
        "{%0,%1,%2,%3}, {%4,%5,%6,%7}, {%8,%9}, {%0,%1,%2,%3};"
        : "+f"(c[0]), "+f"(c[1]), "+f"(c[2]), "+f"(c[3])
        : "r"(a[0]), "r"(a[1]), "r"(a[2]), "r"(a[3]), "r"(b[0]), "r"(b[1]));
}

// ---------------- table init ---------------------------------------------------
__global__ void init_tables() {
    int i = blockIdx.x * blockDim.x + threadIdx.x;
    const float TWO_PI = 6.283185307179586f;
    if (i < 512) {
        float a = TWO_PI * (float)i / 1024.0f;
        g_c1024[i] = cosf(a);
        g_s1024[i] = sinf(a);
    }
    if (i < 256) {
        float a = TWO_PI * (float)i / 512.0f;
        g_c512[i] = cosf(a);
        g_s512[i] = sinf(a);
    }
    if (i < 1024) {
        float w = 0.5f * (1.0f - cosf(TWO_PI * (float)i / 1024.0f));
        g_winS[i] = w * (1.0f / 1024.0f);
        g_win2[i] = w * w;
    }
}

// ---------------- split prep (2 terms) + extra-bin partial dots ---------------------
__device__ __forceinline__ void split2(float v, __nv_bfloat16& h0, __nv_bfloat16& h1) {
    h0 = __float2bfloat16(v);
    h1 = __float2bfloat16(v - __bfloat162float(h0));
}

__global__ void split_x_kernel(const float* __restrict__ x,
                               const float* __restrict__ Wp) {
    __shared__ float tile[32][33];
    __shared__ float w0s[32], w1s[32];
    __shared__ float red0[8][32];
    __shared__ float red1[8][32];
    int b = blockIdx.z;
    int kt = blockIdx.y;
    int k0 = kt * 32, t0 = blockIdx.x * 32;
    int tx = threadIdx.x, ty = threadIdx.y;

    if (ty == 0) {
        w0s[tx] = Wp[(size_t)511 * DIMK + k0 + tx];
        w1s[tx] = Wp[(size_t)512 * DIMK + k0 + tx];
    }
    const float* src = x + ((size_t)b * DIMK + k0) * TT + t0;
    #pragma unroll
    for (int r = 0; r < 4; r++)
        tile[ty + 8 * r][tx] = src[(size_t)(ty + 8 * r) * TT + tx];
    __syncthreads();

    // bf16 splits (transposed read)
    #pragma unroll
    for (int r = 0; r < 4; r++) {
        float v = tile[tx][ty + 8 * r];
        size_t m = (size_t)b * TT + t0 + ty + 8 * r;
        __nv_bfloat16 h0, h1;
        split2(v, h0, h1);
        size_t o = m * DIMK + k0 + tx;
        g_A[o] = h0;
        g_A[ASZ + o] = h1;
    }

    // partial dots for phase bins 511/512 (thread owns t=t0+tx, 4 k-values)
    float s0 = 0.f, s1 = 0.f;
    #pragma unroll
    for (int r = 0; r < 4; r++) {
        int kk = ty + 8 * r;
        float xv = tile[kk][tx];
        s0 = fmaf(xv, w0s[kk], s0);
        s1 = fmaf(xv, w1s[kk], s1);
    }
    red0[ty][tx] = s0;
    red1[ty][tx] = s1;
    __syncthreads();
    if (ty == 0) {
        float a0 = 0.f, a1 = 0.f;
        #pragma unroll
        for (int i = 0; i < 8; i++) {
            a0 += red0[i][tx];
            a1 += red1[i][tx];
        }
        g_part[(size_t)(b * TT + t0 + tx) * NKT + kt] = make_float2(a0, a1);
    }
}

__global__ void extra_reduce(const float* __restrict__ bp) {
    int idx = blockIdx.x * 256 + threadIdx.x;      // b*TT + t
    if (idx >= MTOT) return;
    const float2* p = &g_part[(size_t)idx * NKT];
    float a0 = 0.f, a1 = 0.f;
    #pragma unroll
    for (int i = 0; i < NKT; i++) {
        float2 v = p[i];
        a0 += v.x;
        a1 += v.y;
    }
    const float PI_F = 3.14159265358979323846f;
    size_t row = (size_t)idx * NBP;
    g_frq[row + 511] = fminf(fmaxf(a0 + bp[511], -PI_F), PI_F);
    g_frq[row + 512] = fminf(fmaxf(a1 + bp[512], -PI_F), PI_F);
}

// segment sums for bins 511/512 only (the GEMM epilogue covers bins 0..510)
__global__ void seg511_kernel() {
    int sg = blockIdx.x, b = blockIdx.y;
    int tid = threadIdx.x;          // 64 threads: warp0 -> bin 511, warp1 -> bin 512
    int binsel = tid >> 5;
    int l = tid & 31;
    size_t base = ((size_t)b * TT + (size_t)sg * TSEG) * NBP + 511 + binsel;
    float s = 0.f;
    #pragma unroll
    for (int q = 0; q < 4; q++)
        s += g_frq[base + (size_t)(l * 4 + q) * NBP];
    s += __shfl_down_sync(0xffffffffu, s, 16);
    s += __shfl_down_sync(0xffffffffu, s, 8);
    s += __shfl_down_sync(0xffffffffu, s, 4);
    s += __shfl_down_sync(0xffffffffu, s, 2);
    s += __shfl_down_sync(0xffffffffu, s, 1);
    if (l == 0) g_segsum[b][sg][511 + binsel] = s;
}

__global__ void split_w_kernel(const float* __restrict__ Wm,
                               const float* __restrict__ Wp) {
    int n = blockIdx.x;
    const float* src = (n < NBINS) ? Wm + (size_t)n * DIMK
                                   : Wp + (size_t)(n - NBINS) * DIMK;
    for (int k = threadIdx.x; k < DIMK; k += 256) {
        float v = src[k];
        __nv_bfloat16 h0, h1;
        split2(v, h0, h1);
        size_t o = (size_t)n * DIMK + k;
        g_B[o] = h0;
        g_B[BSZ + o] = h1;
    }
}

// ---------------- HMMA 2-split dual GEMM: 256x128, KC=64, 2-stage (R8 config) -------
// epilogue additionally produces phase segment sums (fused cumsum_seg)
__global__ void __launch_bounds__(NTHR, 1) gemm_hmma(
    const float* __restrict__ bmag, const float* __restrict__ bphs)
{
    extern __shared__ char smraw[];
    uint32_t smem_base = smem_u32(smraw);

    int tid = threadIdx.x;
    int lane = tid & 31, wid = tid >> 5;     // 16 warps: 4x4, 64m x 32n each
    int wm = wid >> 2, wn = wid & 3;
    int n0 = blockIdx.x * TLN;
    int m0 = blockIdx.y * TLM;

    float acc[4][4][4];
    #pragma unroll
    for (int mt = 0; mt < 4; mt++)
        #pragma unroll
        for (int nt = 0; nt < 4; nt++)
            #pragma unroll
            for (int r = 0; r < 4; r++) acc[mt][nt][r] = 0.f;

    uint32_t aoff = (uint32_t)((wm * 64 + (lane & 15)) * SROW + (lane >> 4) * 16);
    uint32_t boff = (uint32_t)((wn * 32 + (lane & 7) + (lane >> 4) * 8) * SROW +
                               ((lane >> 3) & 1) * 16);

    // 6144 cp16 per chunk -> 12 per thread -> 4 parts of 3
    #define ISSUE_PART(k0_, buf_, part_) do {                                         \
        uint32_t stage_ = smem_base + (uint32_t)(buf_) * STAGE_BYTES;                 \
        _Pragma("unroll")                                                             \
        for (int j_ = 0; j_ < 3; j_++) {                                              \
            int v_ = tid + ((part_) * 3 + j_) * NTHR;                                 \
            int isB_ = v_ >= 4096;                                                    \
            int r_ = isB_ ? v_ - 4096 : v_;                                           \
            int p_ = isB_ ? (r_ >> 10) : (r_ >> 11);                                  \
            int rem_ = isB_ ? (r_ & 1023) : (r_ & 2047);                              \
            int row_ = rem_ >> 3;                                                     \
            int ch_ = rem_ & 7;                                                       \
            const __nv_bfloat16* s_ = isB_                                            \
                ? g_B + (size_t)p_ * BSZ + (size_t)(n0 + row_) * DIMK + (k0_) + ch_ * 8 \
                : g_A + (size_t)p_ * ASZ + (size_t)(m0 + row_) * DIMK + (k0_) + ch_ * 8; \
            uint32_t d_ = stage_ +                                                    \
                (isB_ ? (uint32_t)(B_BASE + p_ * B_SPLIT) : (uint32_t)(p_ * A_SPLIT)) \
                + (uint32_t)(row_ * SROW + ch_ * 16);                                 \
            cp16(d_, s_);                                                             \
        }                                                                             \
    } while (0)

    // prologue: chunk 0 -> buf 0
    ISSUE_PART(0, 0, 0);
    ISSUE_PART(0, 0, 1);
    ISSUE_PART(0, 0, 2);
    ISSUE_PART(0, 0, 3);
    CP_COMMIT();

    #pragma unroll 1
    for (int c = 0; c < NCHG; c++) {
        int s = c & 1;
        CP_WAIT0();
        __syncthreads();

        uint32_t sA = smem_base + (uint32_t)s * STAGE_BYTES;
        uint32_t sB = sA + B_BASE;
        int knext = (c + 1) * KC;
        bool more = (c + 1 < NCHG);

        #pragma unroll
        for (int ks = 0; ks < 4; ks++) {
            uint32_t afr[4][4];
            uint32_t bfr0[4][2], bfr1[4][2];

            // B fragments, both splits
            {
                uint32_t bd0 = sB + boff + (uint32_t)(ks * 32);
                ldsm_x4(bfr0[0][0], bfr0[0][1], bfr0[1][0], bfr0[1][1], bd0);
                ldsm_x4(bfr0[2][0], bfr0[2][1], bfr0[3][0], bfr0[3][1], bd0 + 16 * SROW);
                uint32_t bd1 = bd0 + B_SPLIT;
                ldsm_x4(bfr1[0][0], bfr1[0][1], bfr1[1][0], bfr1[1][1], bd1);
                ldsm_x4(bfr1[2][0], bfr1[2][1], bfr1[3][0], bfr1[3][1], bd1 + 16 * SROW);
            }
            // A split 0
            #pragma unroll
            for (int mt = 0; mt < 4; mt++) {
                uint32_t ad = sA + aoff + (uint32_t)(mt * 16 * SROW + ks * 32);
                ldsm_x4(afr[mt][0], afr[mt][1], afr[mt][2], afr[mt][3], ad);
            }

            // front-loaded prefetch of next chunk: parts 0,1 at ks0; 2 at ks1;
            // 3 + commit at ks2 -> full kstep (~1500cyc) before next wait
            if (more && ks == 0) ISSUE_PART(knext, s ^ 1, 0);

            #pragma unroll
            for (int mt = 0; mt < 4; mt++)
                #pragma unroll
                for (int nt = 0; nt < 4; nt++)
                    mma_bf16(acc[mt][nt], afr[mt], bfr0[nt]);   // A0*B0

            if (more) {
                if (ks == 0)      ISSUE_PART(knext, s ^ 1, 1);
                else if (ks == 1) ISSUE_PART(knext, s ^ 1, 2);
                else if (ks == 2) ISSUE_PART(knext, s ^ 1, 3);
            }

            #pragma unroll
            for (int mt = 0; mt < 4; mt++)
                #pragma unroll
                for (int nt = 0; nt < 4; nt++)
                    mma_bf16(acc[mt][nt], afr[mt], bfr1[nt]);   // A0*B1

            if (more && ks == 2) CP_COMMIT();

            // A split 1 (reuse afr regs)
            #pragma unroll
            for (int mt = 0; mt < 4; mt++) {
                uint32_t ad = sA + A_SPLIT + aoff + (uint32_t)(mt * 16 * SROW + ks * 32);
                ldsm_x4(afr[mt][0], afr[mt][1], afr[mt][2], afr[mt][3], ad);
            }
            #pragma unroll
            for (int mt = 0; mt < 4; mt++)
                #pragma unroll
                for (int nt = 0; nt < 4; nt++)
                    mma_bf16(acc[mt][nt], afr[mt], bfr0[nt]);   // A1*B0
        }
    }
    #undef ISSUE_PART

    // epilogue (+ fused phase segment sums; this thread's seg = wm>>1)
    const float PI_F = 3.14159265358979323846f;
    float psum[4][2];
    #pragma unroll
    for (int nt = 0; nt < 4; nt++) { psum[nt][0] = 0.f; psum[nt][1] = 0.f; }

    #pragma unroll
    for (int mt = 0; mt < 4; mt++) {
        #pragma unroll
        for (int nt = 0; nt < 4; nt++) {
            int r0 = m0 + wm * 64 + mt * 16 + (lane >> 2);
            int cg = n0 + wn * 32 + nt * 8 + (lane & 3) * 2;
            #pragma unroll
            for (int hh = 0; hh < 2; hh++) {
                int m = r0 + hh * 8;
                size_t row = (size_t)m * NBP;
                #pragma unroll
                for (int e = 0; e < 2; e++) {
                    int ng = cg + e;
                    float v = acc[mt][nt][hh * 2 + e];
                    if (ng < NBINS) {
                        v += __ldg(bmag + ng);
                        v = fminf(fmaxf(v, -10.f), 10.f);
                        g_mag[row + ng] = __float2half(__expf(v));
                    } else {
                        int nn = ng - NBINS;     // phase bins 0..510
                        v += __ldg(bphs + nn);
                        v = fminf(fmaxf(v, -PI_F), PI_F);
                        g_frq[row + nn] = v;
                        psum[nt][e] += v;
                    }
                }
            }
        }
    }

    // fused segment-sum reduction (phase CTAs: blockIdx.x >= 4)
    bool phaseCTA = (blockIdx.x >= 4);
    float* segsm = reinterpret_cast<float*>(smraw);   // reuse stage smem (256 floats)
    __syncthreads();
    if (tid < 256) segsm[tid] = 0.f;
    __syncthreads();
    if (phaseCTA) {
        int seg = wm >> 1;
        #pragma unroll
        for (int nt = 0; nt < 4; nt++) {
            #pragma unroll
            for (int e = 0; e < 2; e++) {
                float v = psum[nt][e];
                v += __shfl_down_sync(0xffffffffu, v, 16);
                v += __shfl_down_sync(0xffffffffu, v, 8);
                v += __shfl_down_sync(0xffffffffu, v, 4);
                if ((lane >> 2) == 0) {
                    int nl = wn * 32 + nt * 8 + (lane & 3) * 2 + e;
                    atomicAdd(&segsm[seg * 128 + nl], v);
                }
            }
        }
    }
    __syncthreads();
    if (phaseCTA && tid < 256) {
        int seg = tid >> 7, nl = tid & 127;
        int ng = n0 + nl;
        if (ng >= NBINS) {
            int b = m0 >> 11;
            int gseg = ((m0 & (TT - 1)) >> 7) + seg;
            g_segsum[b][gseg][ng - NBINS] = segsm[tid];
        }
    }
}

// ---------------- cumsum: scan of segment sums, then apply ------------------------------
__global__ void cumsum_scan() {
    int n = blockIdx.x * 128 + threadIdx.x;
    int b = blockIdx.y;
    if (n >= NBINS) return;
    float acc = 0.f;
    #pragma unroll
    for (int sg = 0; sg < NSEG; sg++) {
        float v = g_segsum[b][sg][n];
        g_segsum[b][sg][n] = acc;    // exclusive prefix
        acc += v;
    }
}

__global__ void cumsum_apply() {
    int n = blockIdx.x * 128 + threadIdx.x;
    int b = blockIdx.y, sg = blockIdx.z;
    if (n >= NBINS) return;
    float acc = g_segsum[b][sg][n];
    size_t base = ((size_t)b * TT + (size_t)sg * TSEG) * NBP + n;
    #pragma unroll 8
    for (int t = 0; t < TSEG; t++) {
        size_t o = base + (size_t)t * NBP;
        acc += g_frq[o];
        g_frq[o] = acc;
    }
}

// ---------------- frames: real irfft(1024) via 512-pt radix-8 complex IFFT -------------
#define FPB 2
__device__ __forceinline__ int swz(int k) { return k + (k >> 3); }

__global__ __launch_bounds__(128) void frames_kernel() {
    __shared__ float sxr[FPB][513];
    __shared__ float sxi[FPB][513];
    __shared__ float wre[FPB][576];
    __shared__ float wim[FPB][576];
    __shared__ float twr[256];
    __shared__ float twi[256];

    int tid = threadIdx.x;
    int fl = tid >> 6;
    int u  = tid & 63;
    int f = blockIdx.x * FPB + fl;
    size_t base = (size_t)f * NBP;

    for (int i = tid; i < 256; i += 128) {
        twr[i] = g_c512[i];
        twi[i] = g_s512[i];
    }
    for (int n = u; n < 513; n += 64) {
        float mg = __half2float(g_mag[base + n]);
        float ph = g_frq[base + n];
        float s, c;
        __sincosf(ph, &s, &c);
        float im = mg * s;
        if (n == 0 || n == 512) im = 0.f;   // real DC/Nyquist (irfft semantics)
        sxr[fl][n] = mg * c;
        sxi[fl][n] = im;
    }
    __syncthreads();

    #pragma unroll
    for (int q = 0; q < 8; q++) {
        int k = u + q * 64;
        int j = __brev((unsigned)k) >> 23;
        float x0r = sxr[fl][j],       x0i = sxi[fl][j];
        float x1r = sxr[fl][512 - j], x1i = sxi[fl][512 - j];
        float ar = x0r + x1r, ai = x0i - x1i;
        float br = x0r - x1r, bi = x0i + x1i;
        float tr = g_c1024[j], ti = g_s1024[j];
        int kp = swz(k);
        wre[fl][kp] = ar - (tr * bi + ti * br);
        wim[fl][kp] = ai + (tr * br - ti * bi);
    }
    __syncthreads();

    const float S2 = 0.70710678118654752f;
    size_t ob = (size_t)f * NFFT;
    float zr[8], zi[8];

    #pragma unroll
    for (int tt = 0; tt < 3; tt++) {
        const int t = 1 + 3 * tt;
        const int h = 1 << (t - 1);
        int r = u & (h - 1);
        int bi_ = ((u >> (t - 1)) << (t + 2)) | r;
        int k1 = r << (9 - t);

        #pragma unroll
        for (int j = 0; j < 8; j++) {
            int kp = swz(bi_ + j * h);
            zr[j] = wre[fl][kp];
            zi[j] = wim[fl][kp];
        }

        float w1r = twr[k1], w1i = twi[k1];
        #pragma unroll
        for (int q = 0; q < 8; q += 2) {
            float tr_ = zr[q + 1] * w1r - zi[q + 1] * w1i;
            float ti_ = zr[q + 1] * w1i + zi[q + 1] * w1r;
            zr[q + 1] = zr[q] - tr_;  zi[q + 1] = zi[q] - ti_;
            zr[q] += tr_;             zi[q] += ti_;
        }
        float w2r = twr[k1 >> 1], w2i = twi[k1 >> 1];
        #pragma unroll
        for (int g = 0; g < 8; g += 4) {
            float tr0 = zr[g + 2] * w2r - zi[g + 2] * w2i;
            float ti0 = zr[g + 2] * w2i + zi[g + 2] * w2r;
            zr[g + 2] = zr[g] - tr0;  zi[g + 2] = zi[g] - ti0;
            zr[g] += tr0;             zi[g] += ti0;
            float cr = zr[g + 3] * w2r - zi[g + 3] * w2i;
            float ci = zr[g + 3] * w2i + zi[g + 3] * w2r;
            float tr1 = -ci, ti1 = cr;
            zr[g + 3] = zr[g + 1] - tr1;  zi[g + 3] = zi[g + 1] - ti1;
            zr[g + 1] += tr1;             zi[g + 1] += ti1;
        }
        float w3r = twr[k1 >> 2], w3i = twi[k1 >> 2];
        float fr[4], fi[4];
        fr[0] = w3r;                 fi[0] = w3i;
        fr[1] = S2 * (w3r - w3i);    fi[1] = S2 * (w3r + w3i);
        fr[2] = -w3i;                fi[2] = w3r;
        fr[3] = -S2 * (w3r + w3i);   fi[3] = S2 * (w3r - w3i);
        #pragma unroll
        for (int j = 0; j < 4; j++) {
            float tr_ = zr[j + 4] * fr[j] - zi[j + 4] * fi[j];
            float ti_ = zr[j + 4] * fi[j] + zi[j + 4] * fr[j];
            zr[j + 4] = zr[j] - tr_;  zi[j + 4] = zi[j] - ti_;
            zr[j] += tr_;             zi[j] += ti_;
        }

        if (tt < 2) {
            #pragma unroll
            for (int j = 0; j < 8; j++) {
                int kp = swz(bi_ + j * h);
                wre[fl][kp] = zr[j];
                wim[fl][kp] = zi[j];
            }
            __syncthreads();
        } else {
            #pragma unroll
            for (int j = 0; j < 8; j++) {
                int m = u + 64 * j;
                float2 o = make_float2(zr[j] * g_winS[2 * m],
                                       zi[j] * g_winS[2 * m + 1]);
                *reinterpret_cast<__half2*>(&g_frames[ob + 2 * m]) =
                    __float22half2_rn(o);
            }
        }
    }
}

// ---------------- overlap-add (4 samples/thread; interior env == 1.5 exactly) ----------
__global__ void oa_kernel(float* __restrict__ out) {
    int idx4 = blockIdx.x * 256 + threadIdx.x;
    const int GROUPS = OUTLEN / 4;           // 131008
    if (idx4 >= BATCH * GROUPS) return;
    int b = idx4 / GROUPS;
    int s = (idx4 - b * GROUPS) * 4;
    int p = s + NFFT / 2;                    // 4-aligned

    if (p >= NFFT - HOP && p + 3 <= (TT - 1) * HOP + 255) {
        // interior: exactly 4 frames; hann^2 4x-overlap sum == 1.5
        int t0 = (p - (NFFT - HOP)) >> 8;
        float4 sig = make_float4(0.f, 0.f, 0.f, 0.f);
        #pragma unroll
        for (int q = 0; q < 4; q++) {
            int t = t0 + q;
            int j = p - (t << 8);
            const __half2* fp = reinterpret_cast<const __half2*>(
                &g_frames[((size_t)(b * TT + t) << 10) + j]);
            float2 f0 = __half22float2(fp[0]);
            float2 f1 = __half22float2(fp[1]);
            sig.x += f0.x; sig.y += f0.y; sig.z += f1.x; sig.w += f1.y;
        }
        const float INV = 2.0f / 3.0f;
        float4 o;
        o.x = fminf(fmaxf(sig.x * INV, -1.f), 1.f);
        o.y = fminf(fmaxf(sig.y * INV, -1.f), 1.f);
        o.z = fminf(fmaxf(sig.z * INV, -1.f), 1.f);
        o.w = fminf(fmaxf(sig.w * INV, -1.f), 1.f);
        *reinterpret_cast<float4*>(&out[(size_t)b * OUTLEN + s]) = o;
        return;
    }

    int t1 = p >> 8;  if (t1 > TT - 1) t1 = TT - 1;
    int t0 = (p >= NFFT - HOP) ? ((p - (NFFT - HOP)) >> 8) : 0;

    float4 sig = make_float4(0.f, 0.f, 0.f, 0.f);
    float4 env = make_float4(0.f, 0.f, 0.f, 0.f);
    #pragma unroll 4
    for (int t = t0; t <= t1; t++) {
        int j = p - (t << 8);
        const __half2* fp = reinterpret_cast<const __half2*>(
            &g_frames[((size_t)(b * TT + t) << 10) + j]);
        float2 f0 = __half22float2(fp[0]);
        float2 f1 = __half22float2(fp[1]);
        float4 wv = *reinterpret_cast<const float4*>(&g_win2[j]);
        sig.x += f0.x; sig.y += f0.y; sig.z += f1.x; sig.w += f1.y;
        env.x += wv.x; env.y += wv.y; env.z += wv.z; env.w += wv.w;
    }
    float4 o;
    o.x = fminf(fmaxf(sig.x / env.x, -1.f), 1.f);
    o.y = fminf(fmaxf(sig.y / env.y, -1.f), 1.f);
    o.z = fminf(fmaxf(sig.z / env.z, -1.f), 1.f);
    o.w = fminf(fmaxf(sig.w / env.w, -1.f), 1.f);
    *reinterpret_cast<float4*>(&out[(size_t)b * OUTLEN + s]) = o;
}

// ---------------- launcher ----------------------------------------------------------------
extern "C" void kernel_launch(void* const* d_in, const int* in_sizes, int n_in,
                              void* d_out, int out_size) {
    (void)in_sizes; (void)n_in; (void)out_size;
    const float* x  = (const float*)d_in[0];
    const float* Wm = (const float*)d_in[1];
    const float* bm = (const float*)d_in[2];
    const float* Wp = (const float*)d_in[3];
    const float* bp = (const float*)d_in[4];
    float* out = (float*)d_out;

    cudaFuncSetAttribute(gemm_hmma, cudaFuncAttributeMaxDynamicSharedMemorySize,
                         GEMM_SMEM);

    init_tables<<<4, 256>>>();
    split_x_kernel<<<dim3(TT / 32, DIMK / 32, BATCH), dim3(32, 8)>>>(x, Wp);
    split_w_kernel<<<NPAD, 256>>>(Wm, Wp);

    gemm_hmma<<<dim3(NPAD / TLN, MTOT / TLM), NTHR, GEMM_SMEM>>>(bm, bp);
    extra_reduce<<<MTOT / 256, 256>>>(bp);
    seg511_kernel<<<dim3(NSEG, BATCH), 64>>>();

    cumsum_scan<<<dim3(5, BATCH), 128>>>();
    cumsum_apply<<<dim3(5, BATCH, NSEG), 128>>>();

    frames_kernel<<<MTOT / FPB, 128>>>();
    oa_kernel<<<(BATCH * (OUTLEN / 4) + 255) / 256, 256>>>(out);
}